// round 5
// baseline (speedup 1.0000x reference)
#include <cuda_runtime.h>

// ---------------- problem constants ----------------
#define NL   12
#define CC   1024
#define TT   512
#define NH   16
#define HD   64
#define FF   4096
#define BT   2048            // B*T
#define VV   32000
#define BH   64              // B*NH

// ---------------- static device scratch ----------------
__device__ float g_x [BT * CC];
__device__ float g_xn[BT * CC];
__device__ float g_q [BT * CC];
__device__ float g_k [BT * CC];
__device__ float g_v [BT * CC];
__device__ float g_y [BT * CC];
__device__ float g_h [BT * FF];
__device__ float g_att[(size_t)BH * TT * TT];

// ---------------- embedding: x = tok_emb[idx] + pos_emb ----------------
__global__ void embed_kernel(const int* __restrict__ idx,
                             const float* __restrict__ tok,
                             const float* __restrict__ pos,
                             float* __restrict__ x)
{
    int row = blockIdx.x;            // b*T + t
    int t   = row & (TT - 1);
    int id  = idx[row];
    int c   = threadIdx.x * 4;       // 256 threads * 4 = 1024
    float4 tv = *(const float4*)(tok + (size_t)id * CC + c);
    float4 pv = *(const float4*)(pos + (size_t)t  * CC + c);
    float4 o;
    o.x = tv.x + pv.x; o.y = tv.y + pv.y; o.z = tv.z + pv.z; o.w = tv.w + pv.w;
    *(float4*)(x + (size_t)row * CC + c) = o;
}

// ---------------- layernorm (per row of 1024) ----------------
__global__ void ln_kernel(const float* __restrict__ x, float* __restrict__ o,
                          const float* __restrict__ g, const float* __restrict__ b)
{
    int row = blockIdx.x;
    int tid = threadIdx.x;           // 256
    const float* xr = x + (size_t)row * CC;
    float4 xv = *(const float4*)(xr + tid * 4);
    float s  = xv.x + xv.y + xv.z + xv.w;
    float s2 = xv.x*xv.x + xv.y*xv.y + xv.z*xv.z + xv.w*xv.w;
    #pragma unroll
    for (int off = 16; off > 0; off >>= 1) {
        s  += __shfl_xor_sync(0xffffffffu, s,  off);
        s2 += __shfl_xor_sync(0xffffffffu, s2, off);
    }
    __shared__ float sh[16];
    int w = tid >> 5;
    if ((tid & 31) == 0) { sh[w] = s; sh[8 + w] = s2; }
    __syncthreads();
    s = 0.f; s2 = 0.f;
    #pragma unroll
    for (int i = 0; i < 8; i++) { s += sh[i]; s2 += sh[8 + i]; }
    float mean = s * (1.0f / CC);
    float var  = s2 * (1.0f / CC) - mean * mean;
    float rinv = rsqrtf(var + 1e-5f);
    float4 gv = *(const float4*)(g + tid * 4);
    float4 bv = *(const float4*)(b + tid * 4);
    float4 ov;
    ov.x = (xv.x - mean) * rinv * gv.x + bv.x;
    ov.y = (xv.y - mean) * rinv * gv.y + bv.y;
    ov.z = (xv.z - mean) * rinv * gv.z + bv.z;
    ov.w = (xv.w - mean) * rinv * gv.w + bv.w;
    *(float4*)(o + (size_t)row * CC + tid * 4) = ov;
}

// ---------------- SGEMM: C[M,N] = A[M,K] @ B[K,N] (+epilogue) ----------------
// EPI: 0 = none, 1 = +bias, 2 = +bias,relu, 3 = +bias,+residual
// Tiles 128x128x8, 256 threads, 8x8 per thread. M%128==0, N%128==0, K%8==0.
template <int EPI>
__global__ __launch_bounds__(256)
void sgemm_kernel(int M, int N, int K,
                  const float* __restrict__ A,
                  const float* __restrict__ B,
                  float* __restrict__ Cm,
                  const float* __restrict__ bias,
                  const float* __restrict__ resid)
{
    __shared__ float As[8][128];
    __shared__ float Bs[8][128];
    const int bm = blockIdx.y * 128;
    const int bn = blockIdx.x * 128;
    const int tid = threadIdx.x;
    const int arow = tid >> 1;
    const int acol = (tid & 1) << 2;
    const int brow = tid >> 5;
    const int bcol = (tid & 31) << 2;
    const int tx = tid & 15, ty = tid >> 4;

    const float* Ap = A + (size_t)(bm + arow) * K + acol;
    const float* Bp = B + (size_t)brow * N + bn + bcol;

    float acc[8][8];
    #pragma unroll
    for (int i = 0; i < 8; i++)
        #pragma unroll
        for (int j = 0; j < 8; j++) acc[i][j] = 0.f;

    for (int k0 = 0; k0 < K; k0 += 8) {
        float4 av = *(const float4*)(Ap + k0);
        float4 bv = *(const float4*)(Bp + (size_t)k0 * N);
        As[acol + 0][arow] = av.x;
        As[acol + 1][arow] = av.y;
        As[acol + 2][arow] = av.z;
        As[acol + 3][arow] = av.w;
        *(float4*)&Bs[brow][bcol] = bv;
        __syncthreads();
        #pragma unroll
        for (int kk = 0; kk < 8; kk++) {
            float4 a0 = *(const float4*)&As[kk][ty * 8];
            float4 a1 = *(const float4*)&As[kk][ty * 8 + 4];
            float4 b0 = *(const float4*)&Bs[kk][tx * 8];
            float4 b1 = *(const float4*)&Bs[kk][tx * 8 + 4];
            float ra[8] = {a0.x, a0.y, a0.z, a0.w, a1.x, a1.y, a1.z, a1.w};
            float rb[8] = {b0.x, b0.y, b0.z, b0.w, b1.x, b1.y, b1.z, b1.w};
            #pragma unroll
            for (int i = 0; i < 8; i++)
                #pragma unroll
                for (int j = 0; j < 8; j++)
                    acc[i][j] = fmaf(ra[i], rb[j], acc[i][j]);
        }
        __syncthreads();
    }

    #pragma unroll
    for (int i = 0; i < 8; i++) {
        int row = bm + ty * 8 + i;
        size_t base = (size_t)row * N + bn + tx * 8;
        #pragma unroll
        for (int j = 0; j < 8; j += 4) {
            float4 o;
            o.x = acc[i][j]; o.y = acc[i][j + 1]; o.z = acc[i][j + 2]; o.w = acc[i][j + 3];
            if (EPI >= 1) {
                int col = bn + tx * 8 + j;
                o.x += bias[col]; o.y += bias[col + 1]; o.z += bias[col + 2]; o.w += bias[col + 3];
            }
            if (EPI == 2) {
                o.x = fmaxf(o.x, 0.f); o.y = fmaxf(o.y, 0.f);
                o.z = fmaxf(o.z, 0.f); o.w = fmaxf(o.w, 0.f);
            }
            if (EPI == 3) {
                float4 r = *(const float4*)(resid + base + j);
                o.x += r.x; o.y += r.y; o.z += r.z; o.w += r.w;
            }
            *(float4*)(Cm + base + j) = o;
        }
    }
}

// ---------------- causal attention: scores + softmax ----------------
// one block per (b,h,t), 128 threads
__global__ void attn_scores_kernel(const float* __restrict__ q,
                                   const float* __restrict__ k,
                                   float* __restrict__ att)
{
    int t  = blockIdx.x & (TT - 1);
    int bh = blockIdx.x >> 9;
    int b  = bh >> 4, h = bh & 15;
    int tid = threadIdx.x;           // 128
    __shared__ float qs[HD];
    __shared__ float sc[TT];
    __shared__ float red[4];

    const float* qrow = q + ((size_t)(b * TT + t)) * CC + h * HD;
    if (tid < HD) qs[tid] = qrow[tid] * 0.125f;   // HD^-0.5 = 1/8
    __syncthreads();

    float lmax = -1e30f;
    for (int s = tid; s <= t; s += 128) {
        const float* kr = k + ((size_t)(b * TT + s)) * CC + h * HD;
        float d = 0.f;
        #pragma unroll
        for (int i = 0; i < HD; i += 4) {
            float4 kv = *(const float4*)(kr + i);
            d += qs[i] * kv.x + qs[i + 1] * kv.y + qs[i + 2] * kv.z + qs[i + 3] * kv.w;
        }
        sc[s] = d;
        lmax = fmaxf(lmax, d);
    }
    #pragma unroll
    for (int off = 16; off > 0; off >>= 1)
        lmax = fmaxf(lmax, __shfl_xor_sync(0xffffffffu, lmax, off));
    if ((tid & 31) == 0) red[tid >> 5] = lmax;
    __syncthreads();
    float m = fmaxf(fmaxf(red[0], red[1]), fmaxf(red[2], red[3]));
    __syncthreads();

    float lsum = 0.f;
    for (int s = tid; s <= t; s += 128) {
        float e = __expf(sc[s] - m);
        sc[s] = e;
        lsum += e;
    }
    #pragma unroll
    for (int off = 16; off > 0; off >>= 1)
        lsum += __shfl_xor_sync(0xffffffffu, lsum, off);
    if ((tid & 31) == 0) red[tid >> 5] = lsum;
    __syncthreads();
    float inv = 1.0f / (red[0] + red[1] + red[2] + red[3]);

    float* ar = att + ((size_t)bh * TT + t) * TT;
    for (int s = tid; s <= t; s += 128) ar[s] = sc[s] * inv;
}

// ---------------- attention: y = att @ v (per head) ----------------
// one block per (b,h,t), 64 threads (one per head dim)
__global__ void attn_av_kernel(const float* __restrict__ att,
                               const float* __restrict__ v,
                               float* __restrict__ y)
{
    int t  = blockIdx.x & (TT - 1);
    int bh = blockIdx.x >> 9;
    int b  = bh >> 4, h = bh & 15;
    int d  = threadIdx.x;            // 64
    const float* ar = att + ((size_t)bh * TT + t) * TT;
    const float* vb = v + ((size_t)b * TT) * CC + h * HD + d;
    float acc = 0.f;
    int s = 0;
    int lim = t + 1;
    for (; s + 4 <= lim; s += 4) {
        float a0 = ar[s], a1 = ar[s + 1], a2 = ar[s + 2], a3 = ar[s + 3];
        acc += a0 * vb[(size_t)(s)     * CC];
        acc += a1 * vb[(size_t)(s + 1) * CC];
        acc += a2 * vb[(size_t)(s + 2) * CC];
        acc += a3 * vb[(size_t)(s + 3) * CC];
    }
    for (; s < lim; s++) acc += ar[s] * vb[(size_t)s * CC];
    y[((size_t)(b * TT + t)) * CC + h * HD + d] = acc;
}

// ---------------- host launcher ----------------
static float* sym_addr(const void* sym)
{
    void* p = nullptr;
    cudaGetSymbolAddress(&p, sym);
    return (float*)p;
}

extern "C" void kernel_launch(void* const* d_in, const int* in_sizes, int n_in,
                              void* d_out, int out_size)
{
    const int*   idx  = (const int*)  d_in[0];
    const float* tok  = (const float*)d_in[1];
    const float* pos  = (const float*)d_in[2];
    const float* wq   = (const float*)d_in[3];
    const float* wk   = (const float*)d_in[4];
    const float* wv   = (const float*)d_in[5];
    const float* wo   = (const float*)d_in[6];
    const float* bo   = (const float*)d_in[7];
    const float* ln1g = (const float*)d_in[8];
    const float* ln1b = (const float*)d_in[9];
    const float* ln2g = (const float*)d_in[10];
    const float* ln2b = (const float*)d_in[11];
    const float* w1   = (const float*)d_in[12];
    const float* b1   = (const float*)d_in[13];
    const float* w2   = (const float*)d_in[14];
    const float* b2   = (const float*)d_in[15];
    const float* lnfg = (const float*)d_in[16];
    const float* lnfb = (const float*)d_in[17];
    const float* wlm  = (const float*)d_in[18];
    float* out = (float*)d_out;

    float* x   = sym_addr(g_x);
    float* xn  = sym_addr(g_xn);
    float* q   = sym_addr(g_q);
    float* k   = sym_addr(g_k);
    float* v   = sym_addr(g_v);
    float* y   = sym_addr(g_y);
    float* hb  = sym_addr(g_h);
    float* att = sym_addr(g_att);

    embed_kernel<<<BT, 256>>>(idx, tok, pos, x);

    const dim3 gProj(CC / 128, BT / 128);   // (8,16)
    const dim3 gMlp1(FF / 128, BT / 128);   // (32,16)
    const dim3 gLm (VV / 128, BT / 128);    // (250,16)

    for (int l = 0; l < NL; l++) {
        size_t wofs = (size_t)l * CC * CC;
        ln_kernel<<<BT, 256>>>(x, xn, ln1g + l * CC, ln1b + l * CC);
        sgemm_kernel<0><<<gProj, 256>>>(BT, CC, CC, xn, wq + wofs, q, nullptr, nullptr);
        sgemm_kernel<0><<<gProj, 256>>>(BT, CC, CC, xn, wk + wofs, k, nullptr, nullptr);
        sgemm_kernel<0><<<gProj, 256>>>(BT, CC, CC, xn, wv + wofs, v, nullptr, nullptr);
        attn_scores_kernel<<<BH * TT, 128>>>(q, k, att);
        attn_av_kernel<<<BH * TT, 64>>>(att, v, y);
        sgemm_kernel<3><<<gProj, 256>>>(BT, CC, CC, y, wo + wofs, x, bo + l * CC, x);
        ln_kernel<<<BT, 256>>>(x, xn, ln2g + l * CC, ln2b + l * CC);
        sgemm_kernel<2><<<gMlp1, 256>>>(BT, FF, CC, xn, w1 + (size_t)l * CC * FF, hb,
                                        b1 + l * FF, nullptr);
        sgemm_kernel<3><<<gProj, 256>>>(BT, CC, FF, hb, w2 + (size_t)l * FF * CC, x,
                                        b2 + l * CC, x);
    }

    ln_kernel<<<BT, 256>>>(x, xn, lnfg, lnfb);
    sgemm_kernel<0><<<gLm, 256>>>(BT, VV, CC, xn, wlm, out, nullptr, nullptr);
}

// round 6
// speedup vs baseline: 2.1265x; 2.1265x over previous
#include <cuda_runtime.h>
#include <cuda_bf16.h>

// ---------------- problem constants ----------------
#define NL   12
#define CC   1024
#define TT   512
#define NH   16
#define HD   64
#define FF   4096
#define BT   2048            // B*T
#define VV   32000
#define BH   64              // B*NH

// ---------------- GEMM tile config ----------------
#define BM 128
#define BN 128
#define BK 32
#define A_STRIDE 80                        // 32 bf16 = 64B + 16B pad (conflict-free ldmatrix)
#define B_STRIDE 272                       // 128 bf16 = 256B + 16B pad
#define OFF_AH 0
#define OFF_AL (128 * A_STRIDE)            // 10240
#define OFF_BH (2 * 128 * A_STRIDE)        // 20480
#define OFF_BL (OFF_BH + 32 * B_STRIDE)    // 29184
#define STAGE_BYTES (OFF_BL + 32 * B_STRIDE)   // 37888
#define GEMM_SMEM (2 * STAGE_BYTES)        // 75776

// ---------------- static device scratch ----------------
__device__ float g_x [BT * CC];
__device__ float g_xn[BT * CC];
__device__ float g_q [BT * CC];
__device__ float g_k [BT * CC];
__device__ float g_v [BT * CC];
__device__ float g_y [BT * CC];
__device__ float g_h [BT * FF];
__device__ float g_att[(size_t)BH * TT * TT];

// ---------------- mma helpers ----------------
__device__ __forceinline__ unsigned pack_bf16(float x, float y)
{
    __nv_bfloat162 h = __floats2bfloat162_rn(x, y);   // .x in low 16 bits
    return *reinterpret_cast<unsigned*>(&h);
}

// split (x,y) into packed hi and packed lo bf16 pairs: x = hi + lo (+ ~2^-18 x)
__device__ __forceinline__ void split_pair(float x, float y, unsigned& hi, unsigned& lo)
{
    float hx = __bfloat162float(__float2bfloat16(x));
    float hy = __bfloat162float(__float2bfloat16(y));
    hi = pack_bf16(x, y);
    lo = pack_bf16(x - hx, y - hy);   // Sterbenz: exact residual
}

__device__ __forceinline__ void ldsm4(unsigned* r, unsigned a)
{
    asm volatile("ldmatrix.sync.aligned.m8n8.x4.shared.b16 {%0,%1,%2,%3},[%4];"
                 : "=r"(r[0]), "=r"(r[1]), "=r"(r[2]), "=r"(r[3]) : "r"(a));
}
__device__ __forceinline__ void ldsm4t(unsigned* r, unsigned a)
{
    asm volatile("ldmatrix.sync.aligned.m8n8.x4.trans.shared.b16 {%0,%1,%2,%3},[%4];"
                 : "=r"(r[0]), "=r"(r[1]), "=r"(r[2]), "=r"(r[3]) : "r"(a));
}
__device__ __forceinline__ void mma_bf16(float* d, const unsigned* a, const unsigned* b)
{
    asm volatile("mma.sync.aligned.m16n8k16.row.col.f32.bf16.bf16.f32 "
                 "{%0,%1,%2,%3},{%4,%5,%6,%7},{%8,%9},{%0,%1,%2,%3};"
                 : "+f"(d[0]), "+f"(d[1]), "+f"(d[2]), "+f"(d[3])
                 : "r"(a[0]), "r"(a[1]), "r"(a[2]), "r"(a[3]),
                   "r"(b[0]), "r"(b[1]));
}

// ---------------- embedding ----------------
__global__ void embed_kernel(const int* __restrict__ idx,
                             const float* __restrict__ tok,
                             const float* __restrict__ pos,
                             float* __restrict__ x)
{
    int row = blockIdx.x;
    int t   = row & (TT - 1);
    int id  = idx[row];
    int c   = threadIdx.x * 4;
    float4 tv = *(const float4*)(tok + (size_t)id * CC + c);
    float4 pv = *(const float4*)(pos + (size_t)t  * CC + c);
    float4 o;
    o.x = tv.x + pv.x; o.y = tv.y + pv.y; o.z = tv.z + pv.z; o.w = tv.w + pv.w;
    *(float4*)(x + (size_t)row * CC + c) = o;
}

// ---------------- layernorm ----------------
__global__ void ln_kernel(const float* __restrict__ x, float* __restrict__ o,
                          const float* __restrict__ g, const float* __restrict__ b)
{
    int row = blockIdx.x;
    int tid = threadIdx.x;
    const float* xr = x + (size_t)row * CC;
    float4 xv = *(const float4*)(xr + tid * 4);
    float s  = xv.x + xv.y + xv.z + xv.w;
    float s2 = xv.x*xv.x + xv.y*xv.y + xv.z*xv.z + xv.w*xv.w;
    #pragma unroll
    for (int off = 16; off > 0; off >>= 1) {
        s  += __shfl_xor_sync(0xffffffffu, s,  off);
        s2 += __shfl_xor_sync(0xffffffffu, s2, off);
    }
    __shared__ float sh[16];
    int w = tid >> 5;
    if ((tid & 31) == 0) { sh[w] = s; sh[8 + w] = s2; }
    __syncthreads();
    s = 0.f; s2 = 0.f;
    #pragma unroll
    for (int i = 0; i < 8; i++) { s += sh[i]; s2 += sh[8 + i]; }
    float mean = s * (1.0f / CC);
    float var  = s2 * (1.0f / CC) - mean * mean;
    float rinv = rsqrtf(var + 1e-5f);
    float4 gv = *(const float4*)(g + tid * 4);
    float4 bv = *(const float4*)(b + tid * 4);
    float4 ov;
    ov.x = (xv.x - mean) * rinv * gv.x + bv.x;
    ov.y = (xv.y - mean) * rinv * gv.y + bv.y;
    ov.z = (xv.z - mean) * rinv * gv.z + bv.z;
    ov.w = (xv.w - mean) * rinv * gv.w + bv.w;
    *(float4*)(o + (size_t)row * CC + tid * 4) = ov;
}

// ---------------- tensor-core GEMM (fp32 via bf16 hi/lo split, 3 mma passes) ----
// C[M,N] = A[M,K] @ B[K,N] (+epilogue). EPI: 0 none, 2 +bias,relu, 3 +bias+resid
// 128x128x32 tiles, 256 threads (8 warps 2x4), warp tile 64x32, double-buffered.
template <int EPI>
__global__ __launch_bounds__(256)
void bgemm_kernel(int M, int N, int K,
                  const float* __restrict__ A,
                  const float* __restrict__ B,
                  float* __restrict__ Cm,
                  const float* __restrict__ bias,
                  const float* __restrict__ resid)
{
    extern __shared__ char smem[];
    const unsigned sbase = (unsigned)__cvta_generic_to_shared(smem);

    const int tid  = threadIdx.x;
    const int bm   = blockIdx.y * BM;
    const int bn   = blockIdx.x * BN;
    const int warp = tid >> 5;
    const int lane = tid & 31;
    const int wm   = warp >> 2;        // 0..1
    const int wn   = warp & 3;         // 0..3

    // producer mapping
    const int arow = tid >> 3;         // 0..31 (4 passes of 32 rows)
    const int ac4  = tid & 7;          // float4 col within 32-wide A row
    const int brow = tid >> 5;         // 0..7  (4 passes of 8 rows)
    const int bc4  = tid & 31;         // float4 col within 128-wide B row

    const float* Ag = A + (size_t)(bm + arow) * K + ac4 * 4;
    const float* Bg = B + (size_t)brow * N + bn + bc4 * 4;

    float4 pa[4], pb[4];

    auto sts_tile = [&](int s) {
        char* base = smem + s * STAGE_BYTES;
        #pragma unroll
        for (int p = 0; p < 4; p++) {
            unsigned h0, h1, l0, l1;
            split_pair(pa[p].x, pa[p].y, h0, l0);
            split_pair(pa[p].z, pa[p].w, h1, l1);
            char* adst = base + OFF_AH + (arow + p * 32) * A_STRIDE + ac4 * 8;
            *(uint2*)adst                     = make_uint2(h0, h1);
            *(uint2*)(adst + (OFF_AL-OFF_AH)) = make_uint2(l0, l1);
            split_pair(pb[p].x, pb[p].y, h0, l0);
            split_pair(pb[p].z, pb[p].w, h1, l1);
            char* bdst = base + OFF_BH + (brow + p * 8) * B_STRIDE + bc4 * 8;
            *(uint2*)bdst                     = make_uint2(h0, h1);
            *(uint2*)(bdst + (OFF_BL-OFF_BH)) = make_uint2(l0, l1);
        }
    };

    // prologue: tile 0
    #pragma unroll
    for (int p = 0; p < 4; p++) pa[p] = *(const float4*)(Ag + (size_t)(p * 32) * K);
    #pragma unroll
    for (int p = 0; p < 4; p++) pb[p] = *(const float4*)(Bg + (size_t)(p * 8) * N);
    sts_tile(0);
    __syncthreads();

    float acc[4][4][4];
    #pragma unroll
    for (int i = 0; i < 4; i++)
        #pragma unroll
        for (int j = 0; j < 4; j++)
            #pragma unroll
            for (int r = 0; r < 4; r++) acc[i][j][r] = 0.f;

    // consumer fragment addressing (lane-dependent parts)
    const int am   = wm * 64 + (lane & 15);          // A smem row
    const int aKof = (lane >> 4) << 3;               // +8 k for upper half-lanes
    const int bk   = (lane & 15);                    // B smem row (k)
    const int nb   = wn * 32 + ((lane >> 4) << 3);   // B smem col base

    const int kTiles = K / BK;
    int stage = 0;

    for (int kt = 0; kt < kTiles; kt++) {
        if (kt + 1 < kTiles) {
            int k0 = (kt + 1) * BK;
            #pragma unroll
            for (int p = 0; p < 4; p++)
                pa[p] = *(const float4*)(Ag + k0 + (size_t)(p * 32) * K);
            #pragma unroll
            for (int p = 0; p < 4; p++)
                pb[p] = *(const float4*)(Bg + (size_t)(k0 + p * 8) * N);
        }

        const unsigned st = sbase + stage * STAGE_BYTES;
        #pragma unroll
        for (int h = 0; h < 2; h++) {
            unsigned ah[4][4], al[4][4], bh[2][4], bl[2][4];
            const int kc = h * 16 + aKof;            // A k col for this lane
            #pragma unroll
            for (int i = 0; i < 4; i++) {
                unsigned arow_off = (unsigned)((am + i * 16) * A_STRIDE + kc * 2);
                ldsm4(ah[i], st + OFF_AH + arow_off);
                ldsm4(al[i], st + OFF_AL + arow_off);
            }
            const int bkh = h * 16 + bk;
            #pragma unroll
            for (int j = 0; j < 2; j++) {
                unsigned boff = (unsigned)(bkh * B_STRIDE + (nb + j * 16) * 2);
                ldsm4t(bh[j], st + OFF_BH + boff);
                ldsm4t(bl[j], st + OFF_BL + boff);
            }
            #pragma unroll
            for (int i = 0; i < 4; i++) {
                #pragma unroll
                for (int jj = 0; jj < 4; jj++) {
                    const unsigned* bfh = &bh[jj >> 1][(jj & 1) * 2];
                    const unsigned* bfl = &bl[jj >> 1][(jj & 1) * 2];
                    mma_bf16(acc[i][jj], ah[i], bfh);   // hi*hi
                    mma_bf16(acc[i][jj], al[i], bfh);   // lo*hi
                    mma_bf16(acc[i][jj], ah[i], bfl);   // hi*lo
                }
            }
        }

        if (kt + 1 < kTiles) {
            sts_tile(stage ^ 1);
            __syncthreads();
            stage ^= 1;
        }
    }

    // epilogue: d frag = rows {l/4, l/4+8}, cols {2(l%4), +1}
    const int mrow = bm + wm * 64 + (lane >> 2);
    const int ncol = bn + wn * 32 + (lane & 3) * 2;
    #pragma unroll
    for (int i = 0; i < 4; i++) {
        #pragma unroll
        for (int jj = 0; jj < 4; jj++) {
            int r0 = mrow + i * 16;
            int c  = ncol + jj * 8;
            float2 v0 = make_float2(acc[i][jj][0], acc[i][jj][1]);
            float2 v1 = make_float2(acc[i][jj][2], acc[i][jj][3]);
            if (EPI >= 1) {
                float b0v = bias[c], b1v = bias[c + 1];
                v0.x += b0v; v0.y += b1v; v1.x += b0v; v1.y += b1v;
            }
            if (EPI == 2) {
                v0.x = fmaxf(v0.x, 0.f); v0.y = fmaxf(v0.y, 0.f);
                v1.x = fmaxf(v1.x, 0.f); v1.y = fmaxf(v1.y, 0.f);
            }
            size_t o0 = (size_t)r0 * N + c;
            size_t o1 = (size_t)(r0 + 8) * N + c;
            if (EPI == 3) {
                float2 q0 = *(const float2*)(resid + o0);
                float2 q1 = *(const float2*)(resid + o1);
                v0.x += q0.x; v0.y += q0.y; v1.x += q1.x; v1.y += q1.y;
            }
            *(float2*)(Cm + o0) = v0;
            *(float2*)(Cm + o1) = v1;
        }
    }
}

// ---------------- causal attention: scores + softmax ----------------
__global__ void attn_scores_kernel(const float* __restrict__ q,
                                   const float* __restrict__ k,
                                   float* __restrict__ att)
{
    int t  = blockIdx.x & (TT - 1);
    int bh = blockIdx.x >> 9;
    int b  = bh >> 4, h = bh & 15;
    int tid = threadIdx.x;           // 128
    __shared__ float qs[HD];
    __shared__ float sc[TT];
    __shared__ float red[4];

    const float* qrow = q + ((size_t)(b * TT + t)) * CC + h * HD;
    if (tid < HD) qs[tid] = qrow[tid] * 0.125f;
    __syncthreads();

    float lmax = -1e30f;
    for (int s = tid; s <= t; s += 128) {
        const float* kr = k + ((size_t)(b * TT + s)) * CC + h * HD;
        float d = 0.f;
        #pragma unroll
        for (int i = 0; i < HD; i += 4) {
            float4 kv = *(const float4*)(kr + i);
            d += qs[i] * kv.x + qs[i + 1] * kv.y + qs[i + 2] * kv.z + qs[i + 3] * kv.w;
        }
        sc[s] = d;
        lmax = fmaxf(lmax, d);
    }
    #pragma unroll
    for (int off = 16; off > 0; off >>= 1)
        lmax = fmaxf(lmax, __shfl_xor_sync(0xffffffffu, lmax, off));
    if ((tid & 31) == 0) red[tid >> 5] = lmax;
    __syncthreads();
    float m = fmaxf(fmaxf(red[0], red[1]), fmaxf(red[2], red[3]));
    __syncthreads();

    float lsum = 0.f;
    for (int s = tid; s <= t; s += 128) {
        float e = __expf(sc[s] - m);
        sc[s] = e;
        lsum += e;
    }
    #pragma unroll
    for (int off = 16; off > 0; off >>= 1)
        lsum += __shfl_xor_sync(0xffffffffu, lsum, off);
    if ((tid & 31) == 0) red[tid >> 5] = lsum;
    __syncthreads();
    float inv = 1.0f / (red[0] + red[1] + red[2] + red[3]);

    float* ar = att + ((size_t)bh * TT + t) * TT;
    for (int s = tid; s <= t; s += 128) ar[s] = sc[s] * inv;
}

// ---------------- attention: y = att @ v ----------------
__global__ void attn_av_kernel(const float* __restrict__ att,
                               const float* __restrict__ v,
                               float* __restrict__ y)
{
    int t  = blockIdx.x & (TT - 1);
    int bh = blockIdx.x >> 9;
    int b  = bh >> 4, h = bh & 15;
    int d  = threadIdx.x;            // 64
    const float* ar = att + ((size_t)bh * TT + t) * TT;
    const float* vb = v + ((size_t)b * TT) * CC + h * HD + d;
    float acc = 0.f;
    int s = 0;
    int lim = t + 1;
    for (; s + 4 <= lim; s += 4) {
        float a0 = ar[s], a1 = ar[s + 1], a2 = ar[s + 2], a3 = ar[s + 3];
        acc += a0 * vb[(size_t)(s)     * CC];
        acc += a1 * vb[(size_t)(s + 1) * CC];
        acc += a2 * vb[(size_t)(s + 2) * CC];
        acc += a3 * vb[(size_t)(s + 3) * CC];
    }
    for (; s < lim; s++) acc += ar[s] * vb[(size_t)s * CC];
    y[((size_t)(b * TT + t)) * CC + h * HD + d] = acc;
}

// ---------------- host launcher ----------------
static float* sym_addr(const void* sym)
{
    void* p = nullptr;
    cudaGetSymbolAddress(&p, sym);
    return (float*)p;
}

extern "C" void kernel_launch(void* const* d_in, const int* in_sizes, int n_in,
                              void* d_out, int out_size)
{
    const int*   idx  = (const int*)  d_in[0];
    const float* tok  = (const float*)d_in[1];
    const float* pos  = (const float*)d_in[2];
    const float* wq   = (const float*)d_in[3];
    const float* wk   = (const float*)d_in[4];
    const float* wv   = (const float*)d_in[5];
    const float* wo   = (const float*)d_in[6];
    const float* bo   = (const float*)d_in[7];
    const float* ln1g = (const float*)d_in[8];
    const float* ln1b = (const float*)d_in[9];
    const float* ln2g = (const float*)d_in[10];
    const float* ln2b = (const float*)d_in[11];
    const float* w1   = (const float*)d_in[12];
    const float* b1   = (const float*)d_in[13];
    const float* w2   = (const float*)d_in[14];
    const float* b2   = (const float*)d_in[15];
    const float* lnfg = (const float*)d_in[16];
    const float* lnfb = (const float*)d_in[17];
    const float* wlm  = (const float*)d_in[18];
    float* out = (float*)d_out;

    float* x   = sym_addr(g_x);
    float* xn  = sym_addr(g_xn);
    float* q   = sym_addr(g_q);
    float* k   = sym_addr(g_k);
    float* v   = sym_addr(g_v);
    float* y   = sym_addr(g_y);
    float* hb  = sym_addr(g_h);
    float* att = sym_addr(g_att);

    // allow >48KB dynamic smem (idempotent host-side attribute set)
    cudaFuncSetAttribute((const void*)bgemm_kernel<0>,
                         cudaFuncAttributeMaxDynamicSharedMemorySize, GEMM_SMEM);
    cudaFuncSetAttribute((const void*)bgemm_kernel<2>,
                         cudaFuncAttributeMaxDynamicSharedMemorySize, GEMM_SMEM);
    cudaFuncSetAttribute((const void*)bgemm_kernel<3>,
                         cudaFuncAttributeMaxDynamicSharedMemorySize, GEMM_SMEM);

    embed_kernel<<<BT, 256>>>(idx, tok, pos, x);

    const dim3 gProj(CC / BN, BT / BM);   // (8,16)
    const dim3 gMlp1(FF / BN, BT / BM);   // (32,16)
    const dim3 gLm (VV / BN, BT / BM);    // (250,16)

    for (int l = 0; l < NL; l++) {
        size_t wofs = (size_t)l * CC * CC;
        ln_kernel<<<BT, 256>>>(x, xn, ln1g + l * CC, ln1b + l * CC);
        bgemm_kernel<0><<<gProj, 256, GEMM_SMEM>>>(BT, CC, CC, xn, wq + wofs, q, nullptr, nullptr);
        bgemm_kernel<0><<<gProj, 256, GEMM_SMEM>>>(BT, CC, CC, xn, wk + wofs, k, nullptr, nullptr);
        bgemm_kernel<0><<<gProj, 256, GEMM_SMEM>>>(BT, CC, CC, xn, wv + wofs, v, nullptr, nullptr);
        attn_scores_kernel<<<BH * TT, 128>>>(q, k, att);
        attn_av_kernel<<<BH * TT, 64>>>(att, v, y);
        bgemm_kernel<3><<<gProj, 256, GEMM_SMEM>>>(BT, CC, CC, y, wo + wofs, x, bo + l * CC, x);
        ln_kernel<<<BT, 256>>>(x, xn, ln2g + l * CC, ln2b + l * CC);
        bgemm_kernel<2><<<gMlp1, 256, GEMM_SMEM>>>(BT, FF, CC, xn, w1 + (size_t)l * CC * FF, hb,
                                                   b1 + l * FF, nullptr);
        bgemm_kernel<3><<<gProj, 256, GEMM_SMEM>>>(BT, CC, FF, hb, w2 + (size_t)l * FF * CC, x,
                                                   b2 + l * CC, x);
    }

    ln_kernel<<<BT, 256>>>(x, xn, lnfg, lnfb);
    bgemm_kernel<0><<<gLm, 256, GEMM_SMEM>>>(BT, VV, CC, xn, wlm, out, nullptr, nullptr);
}

// round 8
// speedup vs baseline: 3.9920x; 1.8773x over previous
#include <cuda_runtime.h>
#include <cuda_bf16.h>

// ---------------- problem constants ----------------
#define NL   12
#define CC   1024
#define TT   512
#define NH   16
#define HD   64
#define FF   4096
#define BT   2048            // B*T
#define VV   32000
#define BH   64              // B*NH
#define QKVLD 3072           // fused qkv leading dim

// ---------------- GEMM tile config ----------------
#define BM 128
#define BN 128
#define BK 32
#define A_STRIDE 80                        // 32 bf16 = 64B + 16B pad
#define B_STRIDE 272                       // 128 bf16 = 256B + 16B pad
#define OFF_AH 0
#define OFF_AL (128 * A_STRIDE)
#define OFF_BH (2 * 128 * A_STRIDE)
#define OFF_BL (OFF_BH + 32 * B_STRIDE)
#define STAGE_BYTES (OFF_BL + 32 * B_STRIDE)   // 37888
#define GEMM_SMEM (2 * STAGE_BYTES)            // 75776

// ---------------- split-weight layout (elements) ----------------
#define WSZ   (12ull * 1024 * 1024)        // per qkv/o tensor: 12,582,912
#define W1SZ  (12ull * 1024 * 4096)        // 50,331,648
#define WQKV_OFF 0ull                      // 12 layers x [1024 x 3072] concat
#define WO_OFF   (3ull * WSZ)              // 37,748,736
#define W1_OFF   (WO_OFF + WSZ)
#define W2_OFF   (W1_OFF + W1SZ)
#define WLM_OFF  (W2_OFF + W1SZ)
#define WTOT     (WLM_OFF + 1024ull * 32000)

// ---------------- attention smem layout ----------------
#define QS 144                             // 64 bf16 = 128B + 16B pad
#define AT_QH 0
#define AT_QL 18432
#define AT_KH 36864
#define AT_KL 55296
#define AT_VH 73728
#define AT_VL 92160
#define ATTN_SMEM 110592

// ---------------- static device scratch ----------------
__device__ float g_x  [BT * CC];
__device__ float g_xn [BT * CC];
__device__ float g_qkv[BT * QKVLD];
__device__ float g_y  [BT * CC];
__device__ float g_h  [BT * FF];
__device__ __nv_bfloat16 g_whi[WTOT];
__device__ __nv_bfloat16 g_wlo[WTOT];

// ---------------- helpers ----------------
__device__ __forceinline__ unsigned pack_bf16(float x, float y)
{
    __nv_bfloat162 h = __floats2bfloat162_rn(x, y);
    return *reinterpret_cast<unsigned*>(&h);
}

__device__ __forceinline__ void split_pair(float x, float y, unsigned& hi, unsigned& lo)
{
    float hx = __bfloat162float(__float2bfloat16(x));
    float hy = __bfloat162float(__float2bfloat16(y));
    hi = pack_bf16(x, y);
    lo = pack_bf16(x - hx, y - hy);
}

__device__ __forceinline__ void ldsm4(unsigned* r, unsigned a)
{
    asm volatile("ldmatrix.sync.aligned.m8n8.x4.shared.b16 {%0,%1,%2,%3},[%4];"
                 : "=r"(r[0]), "=r"(r[1]), "=r"(r[2]), "=r"(r[3]) : "r"(a));
}
__device__ __forceinline__ void ldsm4t(unsigned* r, unsigned a)
{
    asm volatile("ldmatrix.sync.aligned.m8n8.x4.trans.shared.b16 {%0,%1,%2,%3},[%4];"
                 : "=r"(r[0]), "=r"(r[1]), "=r"(r[2]), "=r"(r[3]) : "r"(a));
}
__device__ __forceinline__ void mma_bf16(float* d, const unsigned* a, unsigned b0, unsigned b1)
{
    asm volatile("mma.sync.aligned.m16n8k16.row.col.f32.bf16.bf16.f32 "
                 "{%0,%1,%2,%3},{%4,%5,%6,%7},{%8,%9},{%0,%1,%2,%3};"
                 : "+f"(d[0]), "+f"(d[1]), "+f"(d[2]), "+f"(d[3])
                 : "r"(a[0]), "r"(a[1]), "r"(a[2]), "r"(a[3]),
                   "r"(b0), "r"(b1));
}

// ---------------- weight split kernels (run each launch; deterministic) ----
__global__ void split_w_kernel(const float* __restrict__ src,
                               __nv_bfloat16* __restrict__ hi,
                               __nv_bfloat16* __restrict__ lo,
                               int n4)
{
    int i = blockIdx.x * 256 + threadIdx.x;
    if (i >= n4) return;
    float4 v = ((const float4*)src)[i];
    unsigned h0, l0, h1, l1;
    split_pair(v.x, v.y, h0, l0);
    split_pair(v.z, v.w, h1, l1);
    ((uint2*)hi)[i] = make_uint2(h0, h1);
    ((uint2*)lo)[i] = make_uint2(l0, l1);
}

// scatter wq/wk/wv (12 x [1024 x 1024]) into concatenated [1024 x 3072] per layer
__global__ void split_w3_kernel(const float* __restrict__ src,
                                __nv_bfloat16* __restrict__ hi,
                                __nv_bfloat16* __restrict__ lo,
                                int cofs)
{
    long i = (long)blockIdx.x * 256 + threadIdx.x;   // float4 index; total WSZ/4
    long e = i * 4;
    long l  = e >> 20;          // / (1024*1024)
    long rm = e & 1048575;
    long kk = rm >> 10;
    long n  = rm & 1023;
    float4 v = ((const float4*)src)[i];
    unsigned h0, l0, h1, l1;
    split_pair(v.x, v.y, h0, l0);
    split_pair(v.z, v.w, h1, l1);
    long d = l * 3145728 + kk * 3072 + cofs + n;     // element offset (mult of 4)
    *(uint2*)(hi + d) = make_uint2(h0, h1);
    *(uint2*)(lo + d) = make_uint2(l0, l1);
}

// ---------------- embedding ----------------
__global__ void embed_kernel(const int* __restrict__ idx,
                             const float* __restrict__ tok,
                             const float* __restrict__ pos,
                             float* __restrict__ x)
{
    int row = blockIdx.x;
    int t   = row & (TT - 1);
    int id  = idx[row];
    int c   = threadIdx.x * 4;
    float4 tv = *(const float4*)(tok + (size_t)id * CC + c);
    float4 pv = *(const float4*)(pos + (size_t)t  * CC + c);
    float4 o;
    o.x = tv.x + pv.x; o.y = tv.y + pv.y; o.z = tv.z + pv.z; o.w = tv.w + pv.w;
    *(float4*)(x + (size_t)row * CC + c) = o;
}

// ---------------- layernorm ----------------
__global__ void ln_kernel(const float* __restrict__ x, float* __restrict__ o,
                          const float* __restrict__ g, const float* __restrict__ b)
{
    int row = blockIdx.x;
    int tid = threadIdx.x;
    const float* xr = x + (size_t)row * CC;
    float4 xv = *(const float4*)(xr + tid * 4);
    float s  = xv.x + xv.y + xv.z + xv.w;
    float s2 = xv.x*xv.x + xv.y*xv.y + xv.z*xv.z + xv.w*xv.w;
    #pragma unroll
    for (int off = 16; off > 0; off >>= 1) {
        s  += __shfl_xor_sync(0xffffffffu, s,  off);
        s2 += __shfl_xor_sync(0xffffffffu, s2, off);
    }
    __shared__ float sh[16];
    int w = tid >> 5;
    if ((tid & 31) == 0) { sh[w] = s; sh[8 + w] = s2; }
    __syncthreads();
    s = 0.f; s2 = 0.f;
    #pragma unroll
    for (int i = 0; i < 8; i++) { s += sh[i]; s2 += sh[8 + i]; }
    float mean = s * (1.0f / CC);
    float var  = s2 * (1.0f / CC) - mean * mean;
    float rinv = rsqrtf(var + 1e-5f);
    float4 gv = *(const float4*)(g + tid * 4);
    float4 bv = *(const float4*)(b + tid * 4);
    float4 ov;
    ov.x = (xv.x - mean) * rinv * gv.x + bv.x;
    ov.y = (xv.y - mean) * rinv * gv.y + bv.y;
    ov.z = (xv.z - mean) * rinv * gv.z + bv.z;
    ov.w = (xv.w - mean) * rinv * gv.w + bv.w;
    *(float4*)(o + (size_t)row * CC + tid * 4) = ov;
}

// ---------------- tensor-core GEMM: A fp32 (split on fly), B pre-split bf16 ---
// C[M,N] = A[M,K] @ B[K,N]. EPI: 0 none, 2 +bias,relu, 3 +bias+resid
template <int EPI>
__global__ __launch_bounds__(256)
void bgemm_kernel(int M, int N, int K,
                  const float* __restrict__ A,
                  const __nv_bfloat16* __restrict__ Bh,
                  const __nv_bfloat16* __restrict__ Bl,
                  float* __restrict__ Cm,
                  const float* __restrict__ bias,
                  const float* __restrict__ resid)
{
    extern __shared__ char smem[];
    const unsigned sbase = (unsigned)__cvta_generic_to_shared(smem);

    const int tid  = threadIdx.x;
    const int bm   = blockIdx.y * BM;
    const int bn   = blockIdx.x * BN;
    const int warp = tid >> 5;
    const int lane = tid & 31;
    const int wm   = warp >> 2;
    const int wn   = warp & 3;

    // producer mapping
    const int arow = tid >> 3;
    const int ac4  = tid & 7;
    const int bi   = tid * 2;
    const int brow = bi >> 4;          // 0..31
    const int bc16 = bi & 15;          // even; thread covers 16 bf16 at col bc16*8

    const float* Ag = A + (size_t)(bm + arow) * K + ac4 * 4;
    const size_t bg = (size_t)brow * N + bn + (size_t)bc16 * 8;

    float4 pa[4];
    uint4  pbh[2], pbl[2];

    auto sts_tile = [&](int s) {
        char* base = smem + s * STAGE_BYTES;
        #pragma unroll
        for (int p = 0; p < 4; p++) {
            unsigned h0, h1, l0, l1;
            split_pair(pa[p].x, pa[p].y, h0, l0);
            split_pair(pa[p].z, pa[p].w, h1, l1);
            char* adst = base + OFF_AH + (arow + p * 32) * A_STRIDE + ac4 * 8;
            *(uint2*)adst                       = make_uint2(h0, h1);
            *(uint2*)(adst + (OFF_AL - OFF_AH)) = make_uint2(l0, l1);
        }
        char* bdst = base + OFF_BH + brow * B_STRIDE + bc16 * 16;
        *(uint4*)bdst        = pbh[0];
        *(uint4*)(bdst + 16) = pbh[1];
        char* ldst = base + OFF_BL + brow * B_STRIDE + bc16 * 16;
        *(uint4*)ldst        = pbl[0];
        *(uint4*)(ldst + 16) = pbl[1];
    };

    // prologue: tile 0
    #pragma unroll
    for (int p = 0; p < 4; p++) pa[p] = *(const float4*)(Ag + (size_t)(p * 32) * K);
    pbh[0] = *(const uint4*)(Bh + bg);
    pbh[1] = *(const uint4*)(Bh + bg + 8);
    pbl[0] = *(const uint4*)(Bl + bg);
    pbl[1] = *(const uint4*)(Bl + bg + 8);
    sts_tile(0);
    __syncthreads();

    float acc[4][4][4];
    #pragma unroll
    for (int i = 0; i < 4; i++)
        #pragma unroll
        for (int j = 0; j < 4; j++)
            #pragma unroll
            for (int r = 0; r < 4; r++) acc[i][j][r] = 0.f;

    const int am   = wm * 64 + (lane & 15);
    const int aKof = (lane >> 4) << 3;
    const int bk   = (lane & 15);
    const int nb   = wn * 32 + ((lane >> 4) << 3);

    const int kTiles = K / BK;
    int stage = 0;

    for (int kt = 0; kt < kTiles; kt++) {
        if (kt + 1 < kTiles) {
            int k0 = (kt + 1) * BK;
            #pragma unroll
            for (int p = 0; p < 4; p++)
                pa[p] = *(const float4*)(Ag + k0 + (size_t)(p * 32) * K);
            size_t bo = bg + (size_t)k0 * N;
            pbh[0] = *(const uint4*)(Bh + bo);
            pbh[1] = *(const uint4*)(Bh + bo + 8);
            pbl[0] = *(const uint4*)(Bl + bo);
            pbl[1] = *(const uint4*)(Bl + bo + 8);
        }

        const unsigned st = sbase + stage * STAGE_BYTES;
        #pragma unroll
        for (int h = 0; h < 2; h++) {
            unsigned ah[4][4], al[4][4], bhf[2][4], blf[2][4];
            const int kc = h * 16 + aKof;
            #pragma unroll
            for (int i = 0; i < 4; i++) {
                unsigned arow_off = (unsigned)((am + i * 16) * A_STRIDE + kc * 2);
                ldsm4(ah[i], st + OFF_AH + arow_off);
                ldsm4(al[i], st + OFF_AL + arow_off);
            }
            const int bkh = h * 16 + bk;
            #pragma unroll
            for (int j = 0; j < 2; j++) {
                unsigned boff = (unsigned)(bkh * B_STRIDE + (nb + j * 16) * 2);
                ldsm4t(bhf[j], st + OFF_BH + boff);
                ldsm4t(blf[j], st + OFF_BL + boff);
            }
            #pragma unroll
            for (int i = 0; i < 4; i++) {
                #pragma unroll
                for (int jj = 0; jj < 4; jj++) {
                    const unsigned* ph = &bhf[jj >> 1][(jj & 1) * 2];
                    const unsigned* pl = &blf[jj >> 1][(jj & 1) * 2];
                    mma_bf16(acc[i][jj], ah[i], ph[0], ph[1]);
                    mma_bf16(acc[i][jj], al[i], ph[0], ph[1]);
                    mma_bf16(acc[i][jj], ah[i], pl[0], pl[1]);
                }
            }
        }

        if (kt + 1 < kTiles) {
            sts_tile(stage ^ 1);
            __syncthreads();
            stage ^= 1;
        }
    }

    const int mrow = bm + wm * 64 + (lane >> 2);
    const int ncol = bn + wn * 32 + (lane & 3) * 2;
    #pragma unroll
    for (int i = 0; i < 4; i++) {
        #pragma unroll
        for (int jj = 0; jj < 4; jj++) {
            int r0 = mrow + i * 16;
            int c  = ncol + jj * 8;
            float2 v0 = make_float2(acc[i][jj][0], acc[i][jj][1]);
            float2 v1 = make_float2(acc[i][jj][2], acc[i][jj][3]);
            if (EPI >= 1) {
                float b0v = bias[c], b1v = bias[c + 1];
                v0.x += b0v; v0.y += b1v; v1.x += b0v; v1.y += b1v;
            }
            if (EPI == 2) {
                v0.x = fmaxf(v0.x, 0.f); v0.y = fmaxf(v0.y, 0.f);
                v1.x = fmaxf(v1.x, 0.f); v1.y = fmaxf(v1.y, 0.f);
            }
            size_t o0 = (size_t)r0 * N + c;
            size_t o1 = (size_t)(r0 + 8) * N + c;
            if (EPI == 3) {
                float2 q0 = *(const float2*)(resid + o0);
                float2 q1 = *(const float2*)(resid + o1);
                v0.x += q0.x; v0.y += q0.y; v1.x += q1.x; v1.y += q1.y;
            }
            *(float2*)(Cm + o0) = v0;
            *(float2*)(Cm + o1) = v1;
        }
    }
}

// ---------------- fused flash attention (split-bf16 mma, online softmax) ----
// grid (4 qtiles, 64 bh), 256 threads = 8 warps; warp w owns q rows w*16..+15
__global__ __launch_bounds__(256)
void attn_kernel(const float* __restrict__ qp,
                 const float* __restrict__ kp,
                 const float* __restrict__ vp,
                 float* __restrict__ y)
{
    extern __shared__ char sm[];
    const unsigned sb = (unsigned)__cvta_generic_to_shared(sm);
    const int qt   = blockIdx.x;
    const int bh   = blockIdx.y;
    const int b    = bh >> 4, h = bh & 15;
    const int tid  = threadIdx.x;
    const int warp = tid >> 5, lane = tid & 31;

    const int    qbase   = qt * 128;
    const size_t rowbase = (size_t)b * TT;
    const int    colh    = h * HD;

    // ---- load + split Q tile (scaled by 1/8) ----
    for (int i = tid; i < 2048; i += 256) {
        int r = i >> 4, c4 = i & 15;
        float4 qv = *(const float4*)(qp + (rowbase + qbase + r) * QKVLD + colh + c4 * 4);
        qv.x *= 0.125f; qv.y *= 0.125f; qv.z *= 0.125f; qv.w *= 0.125f;
        unsigned h0, l0, h1, l1;
        split_pair(qv.x, qv.y, h0, l0);
        split_pair(qv.z, qv.w, h1, l1);
        *(uint2*)(sm + AT_QH + r * QS + c4 * 8) = make_uint2(h0, h1);
        *(uint2*)(sm + AT_QL + r * QS + c4 * 8) = make_uint2(l0, l1);
    }
    __syncthreads();

    // ---- preload Q fragments (reused across kv tiles) ----
    unsigned qh[4][4], ql[4][4];
    {
        int rr = warp * 16 + (lane & 15);
        int kc = (lane >> 4) << 3;
        #pragma unroll
        for (int ks = 0; ks < 4; ks++) {
            unsigned off = (unsigned)(rr * QS + (ks * 16 + kc) * 2);
            ldsm4(qh[ks], sb + AT_QH + off);
            ldsm4(ql[ks], sb + AT_QL + off);
        }
    }

    float Oc[8][4];
    #pragma unroll
    for (int f = 0; f < 8; f++)
        #pragma unroll
        for (int r = 0; r < 4; r++) Oc[f][r] = 0.f;
    float m0 = -1e30f, m8 = -1e30f, l0s = 0.f, l8s = 0.f;

    for (int jt = 0; jt <= qt; jt++) {
        const int jbase = jt * 128;
        __syncthreads();   // prior iteration's smem reads complete
        // ---- load + split K,V tiles ----
        for (int i = tid; i < 2048; i += 256) {
            int r = i >> 4, c4 = i & 15;
            size_t g = (rowbase + jbase + r) * QKVLD + colh + c4 * 4;
            float4 kv = *(const float4*)(kp + g);
            unsigned h0, l0, h1, l1;
            split_pair(kv.x, kv.y, h0, l0);
            split_pair(kv.z, kv.w, h1, l1);
            *(uint2*)(sm + AT_KH + r * QS + c4 * 8) = make_uint2(h0, h1);
            *(uint2*)(sm + AT_KL + r * QS + c4 * 8) = make_uint2(l0, l1);
            float4 vv = *(const float4*)(vp + g);
            split_pair(vv.x, vv.y, h0, l0);
            split_pair(vv.z, vv.w, h1, l1);
            *(uint2*)(sm + AT_VH + r * QS + c4 * 8) = make_uint2(h0, h1);
            *(uint2*)(sm + AT_VL + r * QS + c4 * 8) = make_uint2(l0, l1);
        }
        __syncthreads();

        // ---- S = Q K^T (16 x 128 per warp) ----
        float s[16][4];
        #pragma unroll
        for (int f = 0; f < 16; f++)
            #pragma unroll
            for (int r = 0; r < 4; r++) s[f][r] = 0.f;

        #pragma unroll
        for (int ks = 0; ks < 4; ks++) {
            #pragma unroll
            for (int ng = 0; ng < 8; ng++) {
                unsigned off = (unsigned)((ng * 16 + (lane & 15)) * QS +
                                          (ks * 16 + ((lane >> 4) << 3)) * 2);
                unsigned kh4[4], kl4[4];
                ldsm4(kh4, sb + AT_KH + off);
                ldsm4(kl4, sb + AT_KL + off);
                mma_bf16(s[2*ng],   qh[ks], kh4[0], kh4[2]);
                mma_bf16(s[2*ng],   ql[ks], kh4[0], kh4[2]);
                mma_bf16(s[2*ng],   qh[ks], kl4[0], kl4[2]);
                mma_bf16(s[2*ng+1], qh[ks], kh4[1], kh4[3]);
                mma_bf16(s[2*ng+1], ql[ks], kh4[1], kh4[3]);
                mma_bf16(s[2*ng+1], qh[ks], kl4[1], kl4[3]);
            }
        }

        // ---- causal mask (diagonal tile only) ----
        if (jt == qt) {
            int r0 = warp * 16 + (lane >> 2);
            #pragma unroll
            for (int f = 0; f < 16; f++) {
                int c = f * 8 + 2 * (lane & 3);
                if (c     > r0)     s[f][0] = -1e30f;
                if (c + 1 > r0)     s[f][1] = -1e30f;
                if (c     > r0 + 8) s[f][2] = -1e30f;
                if (c + 1 > r0 + 8) s[f][3] = -1e30f;
            }
        }

        // ---- online softmax ----
        float mx0 = -1e30f, mx8 = -1e30f;
        #pragma unroll
        for (int f = 0; f < 16; f++) {
            mx0 = fmaxf(mx0, fmaxf(s[f][0], s[f][1]));
            mx8 = fmaxf(mx8, fmaxf(s[f][2], s[f][3]));
        }
        mx0 = fmaxf(mx0, __shfl_xor_sync(0xffffffffu, mx0, 1));
        mx0 = fmaxf(mx0, __shfl_xor_sync(0xffffffffu, mx0, 2));
        mx8 = fmaxf(mx8, __shfl_xor_sync(0xffffffffu, mx8, 1));
        mx8 = fmaxf(mx8, __shfl_xor_sync(0xffffffffu, mx8, 2));
        float nm0 = fmaxf(m0, mx0), nm8 = fmaxf(m8, mx8);
        float a0 = __expf(m0 - nm0), a8 = __expf(m8 - nm8);

        float sum0 = 0.f, sum8 = 0.f;
        #pragma unroll
        for (int f = 0; f < 16; f++) {
            s[f][0] = __expf(s[f][0] - nm0);
            s[f][1] = __expf(s[f][1] - nm0);
            s[f][2] = __expf(s[f][2] - nm8);
            s[f][3] = __expf(s[f][3] - nm8);
            sum0 += s[f][0] + s[f][1];
            sum8 += s[f][2] + s[f][3];
        }
        sum0 += __shfl_xor_sync(0xffffffffu, sum0, 1);
        sum0 += __shfl_xor_sync(0xffffffffu, sum0, 2);
        sum8 += __shfl_xor_sync(0xffffffffu, sum8, 1);
        sum8 += __shfl_xor_sync(0xffffffffu, sum8, 2);
        l0s = l0s * a0 + sum0;
        l8s = l8s * a8 + sum8;
        m0 = nm0; m8 = nm8;
        #pragma unroll
        for (int f = 0; f < 8; f++) {
            Oc[f][0] *= a0; Oc[f][1] *= a0;
            Oc[f][2] *= a8; Oc[f][3] *= a8;
        }

        // ---- O += P V ----
        #pragma unroll
        for (int ks = 0; ks < 8; ks++) {
            unsigned ph[4], pl[4];
            split_pair(s[2*ks][0],   s[2*ks][1],   ph[0], pl[0]);
            split_pair(s[2*ks][2],   s[2*ks][3],   ph[1], pl[1]);
            split_pair(s[2*ks+1][0], s[2*ks+1][1], ph[2], pl[2]);
            split_pair(s[2*ks+1][2], s[2*ks+1][3], ph[3], pl[3]);
            #pragma unroll
            for (int ng = 0; ng < 4; ng++) {
                unsigned off = (unsigned)((ks * 16 + (lane & 15)) * QS +
                                          (ng * 16 + ((lane >> 4) << 3)) * 2);
                unsigned vh4[4], vl4[4];
                ldsm4t(vh4, sb + AT_VH + off);
                ldsm4t(vl4, sb + AT_VL + off);
                mma_bf16(Oc[2*ng],   ph, vh4[0], vh4[1]);
                mma_bf16(Oc[2*ng],   pl, vh4[0], vh4[1]);
                mma_bf16(Oc[2*ng],   ph, vl4[0], vl4[1]);
                mma_bf16(Oc[2*ng+1], ph, vh4[2], vh4[3]);
                mma_bf16(Oc[2*ng+1], pl, vh4[2], vh4[3]);
                mma_bf16(Oc[2*ng+1], ph, vl4[2], vl4[3]);
            }
        }
    }

    // ---- normalize + store ----
    float i0 = 1.f / l0s, i8 = 1.f / l8s;
    int r0 = qbase + warp * 16 + (lane >> 2);
    #pragma unroll
    for (int f = 0; f < 8; f++) {
        int c = colh + f * 8 + 2 * (lane & 3);
        *(float2*)(y + (rowbase + r0)     * CC + c) = make_float2(Oc[f][0] * i0, Oc[f][1] * i0);
        *(float2*)(y + (rowbase + r0 + 8) * CC + c) = make_float2(Oc[f][2] * i8, Oc[f][3] * i8);
    }
}

// ---------------- host launcher ----------------
template <typename T>
static T* sym_addr(const void* sym)
{
    void* p = nullptr;
    cudaGetSymbolAddress(&p, sym);
    return (T*)p;
}

extern "C" void kernel_launch(void* const* d_in, const int* in_sizes, int n_in,
                              void* d_out, int out_size)
{
    const int*   idx  = (const int*)  d_in[0];
    const float* tok  = (const float*)d_in[1];
    const float* pos  = (const float*)d_in[2];
    const float* wq   = (const float*)d_in[3];
    const float* wk   = (const float*)d_in[4];
    const float* wv   = (const float*)d_in[5];
    const float* wo   = (const float*)d_in[6];
    const float* bo   = (const float*)d_in[7];
    const float* ln1g = (const float*)d_in[8];
    const float* ln1b = (const float*)d_in[9];
    const float* ln2g = (const float*)d_in[10];
    const float* ln2b = (const float*)d_in[11];
    const float* w1   = (const float*)d_in[12];
    const float* b1   = (const float*)d_in[13];
    const float* w2   = (const float*)d_in[14];
    const float* b2   = (const float*)d_in[15];
    const float* lnfg = (const float*)d_in[16];
    const float* lnfb = (const float*)d_in[17];
    const float* wlm  = (const float*)d_in[18];
    float* out = (float*)d_out;

    float* x   = sym_addr<float>(g_x);
    float* xn  = sym_addr<float>(g_xn);
    float* qkv = sym_addr<float>(g_qkv);
    float* y   = sym_addr<float>(g_y);
    float* hb  = sym_addr<float>(g_h);
    __nv_bfloat16* whi = sym_addr<__nv_bfloat16>(g_whi);
    __nv_bfloat16* wlo = sym_addr<__nv_bfloat16>(g_wlo);

    cudaFuncSetAttribute((const void*)bgemm_kernel<0>,
                         cudaFuncAttributeMaxDynamicSharedMemorySize, GEMM_SMEM);
    cudaFuncSetAttribute((const void*)bgemm_kernel<2>,
                         cudaFuncAttributeMaxDynamicSharedMemorySize, GEMM_SMEM);
    cudaFuncSetAttribute((const void*)bgemm_kernel<3>,
                         cudaFuncAttributeMaxDynamicSharedMemorySize, GEMM_SMEM);
    cudaFuncSetAttribute((const void*)attn_kernel,
                         cudaFuncAttributeMaxDynamicSharedMemorySize, ATTN_SMEM);

    // ---- pre-split all weights into bf16 hi/lo ----
    split_w3_kernel<<<12288, 256>>>(wq, whi, wlo, 0);
    split_w3_kernel<<<12288, 256>>>(wk, whi, wlo, 1024);
    split_w3_kernel<<<12288, 256>>>(wv, whi, wlo, 2048);
    split_w_kernel<<<12288, 256>>>(wo,  whi + WO_OFF,  wlo + WO_OFF,  (int)(WSZ / 4));
    split_w_kernel<<<49152, 256>>>(w1,  whi + W1_OFF,  wlo + W1_OFF,  (int)(W1SZ / 4));
    split_w_kernel<<<49152, 256>>>(w2,  whi + W2_OFF,  wlo + W2_OFF,  (int)(W1SZ / 4));
    split_w_kernel<<<32000, 256>>>(wlm, whi + WLM_OFF, wlo + WLM_OFF, 8192000);

    embed_kernel<<<BT, 256>>>(idx, tok, pos, x);

    const dim3 gQkv (QKVLD / BN, BT / BM);  // (24,16)
    const dim3 gProj(CC / BN, BT / BM);     // (8,16)
    const dim3 gMlp1(FF / BN, BT / BM);     // (32,16)
    const dim3 gLm  (VV / BN, BT / BM);     // (250,16)
    const dim3 gAtt (4, BH);                // (4,64)

    for (int l = 0; l < NL; l++) {
        size_t o3 = (size_t)l * 3145728;            // qkv weights per layer
        size_t oo = WO_OFF + (size_t)l * 1048576;
        size_t o1 = W1_OFF + (size_t)l * 4194304;
        size_t o2 = W2_OFF + (size_t)l * 4194304;

        ln_kernel<<<BT, 256>>>(x, xn, ln1g + l * CC, ln1b + l * CC);
        bgemm_kernel<0><<<gQkv, 256, GEMM_SMEM>>>(BT, QKVLD, CC, xn,
                                                  whi + o3, wlo + o3, qkv, nullptr, nullptr);
        attn_kernel<<<gAtt, 256, ATTN_SMEM>>>(qkv, qkv + 1024, qkv + 2048, y);
        bgemm_kernel<3><<<gProj, 256, GEMM_SMEM>>>(BT, CC, CC, y,
                                                   whi + oo, wlo + oo, x, bo + l * CC, x);
        ln_kernel<<<BT, 256>>>(x, xn, ln2g + l * CC, ln2b + l * CC);
        bgemm_kernel<2><<<gMlp1, 256, GEMM_SMEM>>>(BT, FF, CC, xn,
                                                   whi + o1, wlo + o1, hb, b1 + l * FF, nullptr);
        bgemm_kernel<3><<<gProj, 256, GEMM_SMEM>>>(BT, CC, FF, hb,
                                                   whi + o2, wlo + o2, x, b2 + l * CC, x);
    }

    ln_kernel<<<BT, 256>>>(x, xn, lnfg, lnfb);
    bgemm_kernel<0><<<gLm, 256, GEMM_SMEM>>>(BT, VV, CC, xn,
                                             whi + WLM_OFF, wlo + WLM_OFF, out, nullptr, nullptr);
}